// round 1
// baseline (speedup 1.0000x reference)
#include <cuda_runtime.h>
#include <cstdint>
#include <cstddef>

#define T_SEQ   2048
#define HID     1536
#define NH      12
#define DK      128
#define DV      128
#define KEY_DIM 1536
#define VAL_DIM 1536
#define CONV_K  4
#define GRED    192              // HID / 8
#define WCONV_N (VAL_DIM * CONV_K)  // 6144

// ---------------- scratch (static device allocations are allowed) ----------
__device__ float g_q   [T_SEQ * KEY_DIM];
__device__ float g_k   [T_SEQ * KEY_DIM];
__device__ float g_vpre[T_SEQ * VAL_DIM];
__device__ float g_v   [T_SEQ * VAL_DIM];
__device__ float g_gate[T_SEQ * VAL_DIM];
__device__ float g_g1  [T_SEQ * GRED];
__device__ float g_wc  [T_SEQ * WCONV_N];
__device__ float g_beta[T_SEQ * NH];
__device__ float g_gdec[T_SEQ * NH];
__device__ float g_o   [T_SEQ * VAL_DIM];
__device__ float g_on  [T_SEQ * VAL_DIM];

__device__ __forceinline__ float siluf(float x)    { return x / (1.f + __expf(-x)); }
__device__ __forceinline__ float sigmoidf_(float x){ return 1.f / (1.f + __expf(-x)); }

#define ACT_NONE    0
#define ACT_SILU    1

// ---------------- tiled fp32 GEMM:  C = act(A[MxK] @ B[KxN]) ---------------
// BM=BN=128, BK=16, 256 threads, 8x8 register tile per thread.
__global__ __launch_bounds__(256) void gemm_act_kernel(
    const float* __restrict__ A, const float* __restrict__ B, float* __restrict__ C,
    int M, int N, int K, int act)
{
    __shared__ float As[16][132];   // padded: transposed A tile
    __shared__ float Bs[16][128];

    const int tid = threadIdx.x;
    const int tx  = tid & 15;       // 0..15 -> 8 output cols
    const int ty  = tid >> 4;       // 0..15 -> 8 output rows
    const int row0 = blockIdx.y * 128;
    const int col0 = blockIdx.x * 128;

    float acc[8][8];
#pragma unroll
    for (int i = 0; i < 8; i++)
#pragma unroll
        for (int j = 0; j < 8; j++) acc[i][j] = 0.f;

    const int ktiles = K >> 4;
    for (int kt = 0; kt < ktiles; kt++) {
        // A tile: 128 rows x 16 cols, 512 float4, 2 per thread, stored transposed
#pragma unroll
        for (int l = 0; l < 2; l++) {
            int idx = tid + l * 256;          // 0..511
            int r   = idx >> 2;               // 0..127
            int cq  = (idx & 3) << 2;         // 0,4,8,12
            float4 av = *(const float4*)&A[(size_t)(row0 + r) * K + kt * 16 + cq];
            As[cq + 0][r] = av.x; As[cq + 1][r] = av.y;
            As[cq + 2][r] = av.z; As[cq + 3][r] = av.w;
        }
        // B tile: 16 rows x 128 cols, scalar guarded loads (8 per thread)
#pragma unroll
        for (int l = 0; l < 8; l++) {
            int idx = tid + l * 256;          // 0..2047
            int kk  = idx >> 7;
            int n   = idx & 127;
            int col = col0 + n;
            Bs[kk][n] = (col < N) ? B[(size_t)(kt * 16 + kk) * N + col] : 0.f;
        }
        __syncthreads();

#pragma unroll
        for (int kk = 0; kk < 16; kk++) {
            float4 a0 = *(const float4*)&As[kk][ty * 8];
            float4 a1 = *(const float4*)&As[kk][ty * 8 + 4];
            float4 b0 = *(const float4*)&Bs[kk][tx * 8];
            float4 b1 = *(const float4*)&Bs[kk][tx * 8 + 4];
            float a[8] = {a0.x, a0.y, a0.z, a0.w, a1.x, a1.y, a1.z, a1.w};
            float b[8] = {b0.x, b0.y, b0.z, b0.w, b1.x, b1.y, b1.z, b1.w};
#pragma unroll
            for (int i = 0; i < 8; i++)
#pragma unroll
                for (int j = 0; j < 8; j++)
                    acc[i][j] = fmaf(a[i], b[j], acc[i][j]);
        }
        __syncthreads();
    }

#pragma unroll
    for (int i = 0; i < 8; i++) {
        int r = row0 + ty * 8 + i;
#pragma unroll
        for (int j = 0; j < 8; j++) {
            int c = col0 + tx * 8 + j;
            if (c < N) {
                float v = acc[i][j];
                if (act == ACT_SILU) v = siluf(v);
                C[(size_t)r * N + c] = v;
            }
        }
    }
}

// ------- fused tiny projections: beta = sigmoid(hs@Wb), g = -e^{A}sp(hs@Wa+b)
__global__ __launch_bounds__(256) void small_proj_kernel(
    const float* __restrict__ hs, const float* __restrict__ Wb,
    const float* __restrict__ Wa, const float* __restrict__ A_log,
    const float* __restrict__ dt_bias,
    float* __restrict__ beta, float* __restrict__ gdec)
{
    __shared__ float row[HID];
    const int t = blockIdx.x;
    for (int i = threadIdx.x; i < HID; i += blockDim.x)
        row[i] = hs[(size_t)t * HID + i];
    __syncthreads();

    const int warp = threadIdx.x >> 5;
    const int lane = threadIdx.x & 31;
    for (int oidx = warp; oidx < 2 * NH; oidx += 8) {
        const int  h   = oidx % NH;
        const bool isA = (oidx >= NH);
        const float* W = isA ? Wa : Wb;
        float s = 0.f;
        for (int kk = lane; kk < HID; kk += 32)
            s = fmaf(row[kk], W[(size_t)kk * NH + h], s);
#pragma unroll
        for (int off = 16; off; off >>= 1)
            s += __shfl_xor_sync(0xffffffffu, s, off);
        if (lane == 0) {
            if (isA) {
                float x  = s + dt_bias[h];
                float sp = (x > 20.f) ? x : log1pf(__expf(x));
                gdec[t * NH + h] = -__expf(A_log[h]) * sp;
            } else {
                beta[t * NH + h] = 1.f / (1.f + __expf(-s));
            }
        }
    }
}

// -------- dynamic causal depthwise conv: v[t,d] = silu(sum_i vpre[t+i-3,d]*w[t,d,i])
__global__ __launch_bounds__(256) void conv_kernel(
    const float* __restrict__ vpre, const float* __restrict__ w,
    float* __restrict__ vout)
{
    int idx = blockIdx.x * blockDim.x + threadIdx.x;
    if (idx >= T_SEQ * VAL_DIM) return;
    int t = idx / VAL_DIM;
    int d = idx - t * VAL_DIM;
    float4 wv = *(const float4*)&w[(size_t)t * WCONV_N + d * 4];
    float acc = 0.f;
    if (t >= 3) acc = fmaf(vpre[(size_t)(t - 3) * VAL_DIM + d], wv.x, acc);
    if (t >= 2) acc = fmaf(vpre[(size_t)(t - 2) * VAL_DIM + d], wv.y, acc);
    if (t >= 1) acc = fmaf(vpre[(size_t)(t - 1) * VAL_DIM + d], wv.z, acc);
    acc = fmaf(vpre[(size_t)t * VAL_DIM + d], wv.w, acc);
    vout[idx] = siluf(acc);
}

// ---------------- gated delta-rule scan -----------------------------------
// grid (12 heads, 8 v-slices); block 256 threads.
// thread (vl = tid>>4, kg = tid&15) owns S[kg*8 .. kg*8+7][v0+vl]  (8 regs)
#define SCH 16   // time-chunk staged in shared
#define VPB 16   // v-columns per block
__global__ __launch_bounds__(256) void scan_kernel(
    const float* __restrict__ q, const float* __restrict__ k,
    const float* __restrict__ v, const float* __restrict__ g,
    const float* __restrict__ beta, float* __restrict__ o)
{
    const int h  = blockIdx.x;
    const int v0 = blockIdx.y * VPB;
    const int tid = threadIdx.x;
    const int vl  = tid >> 4;
    const int kg  = tid & 15;

    __shared__ float ksh[SCH][128];
    __shared__ float qsh[SCH][128];
    __shared__ float vsh[SCH][VPB];
    __shared__ float egs[SCH];
    __shared__ float bts[SCH];

    float S[8];
#pragma unroll
    for (int j = 0; j < 8; j++) S[j] = 0.f;

    const float scale = 0.08838834764831845f;  // 128^-0.5

    for (int t0 = 0; t0 < T_SEQ; t0 += SCH) {
#pragma unroll
        for (int l = 0; l < (SCH * 128) / 256; l++) {
            int idx = tid + l * 256;
            int tt = idx >> 7, kk = idx & 127;
            size_t src = (size_t)(t0 + tt) * KEY_DIM + h * DK + kk;
            ksh[tt][kk] = k[src];
            qsh[tt][kk] = q[src];
        }
        {
            int tt = tid >> 4, vv = tid & 15;   // 256 = SCH*VPB exactly
            vsh[tt][vv] = v[(size_t)(t0 + tt) * VAL_DIM + h * DV + v0 + vv];
        }
        if (tid < SCH) {
            egs[tid] = __expf(g[(t0 + tid) * NH + h]);
            bts[tid] = beta[(t0 + tid) * NH + h];
        }
        __syncthreads();

#pragma unroll 4
        for (int tt = 0; tt < SCH; tt++) {
            const float eg = egs[tt];
            const float bt = bts[tt];
            float kr[8], qr[8];
            *(float4*)&kr[0] = *(const float4*)&ksh[tt][kg * 8];
            *(float4*)&kr[4] = *(const float4*)&ksh[tt][kg * 8 + 4];
            *(float4*)&qr[0] = *(const float4*)&qsh[tt][kg * 8];
            *(float4*)&qr[4] = *(const float4*)&qsh[tt][kg * 8 + 4];

            // decay + k^T S partial (two accumulators for ILP)
            float pa = 0.f, pb = 0.f;
#pragma unroll
            for (int j = 0; j < 8; j += 2) {
                S[j]     *= eg; pa = fmaf(kr[j],     S[j],     pa);
                S[j + 1] *= eg; pb = fmaf(kr[j + 1], S[j + 1], pb);
            }
            float p = pa + pb;
            p += __shfl_xor_sync(0xffffffffu, p, 1);
            p += __shfl_xor_sync(0xffffffffu, p, 2);
            p += __shfl_xor_sync(0xffffffffu, p, 4);
            p += __shfl_xor_sync(0xffffffffu, p, 8);

            const float delta = (vsh[tt][vl] - p) * bt;

            float oa = 0.f, ob = 0.f;
#pragma unroll
            for (int j = 0; j < 8; j += 2) {
                S[j]     = fmaf(kr[j],     delta, S[j]);
                oa       = fmaf(qr[j],     S[j],  oa);
                S[j + 1] = fmaf(kr[j + 1], delta, S[j + 1]);
                ob       = fmaf(qr[j + 1], S[j + 1], ob);
            }
            float op = oa + ob;
            op += __shfl_xor_sync(0xffffffffu, op, 1);
            op += __shfl_xor_sync(0xffffffffu, op, 2);
            op += __shfl_xor_sync(0xffffffffu, op, 4);
            op += __shfl_xor_sync(0xffffffffu, op, 8);

            if (kg == 0)
                o[(size_t)(t0 + tt) * VAL_DIM + h * DV + v0 + vl] = op * scale;
        }
        __syncthreads();
    }
}

// ------- gated RMSNorm: on = o * rsqrt(mean(o^2)+eps) * nw * silu(gate) ----
__global__ __launch_bounds__(256) void rmsgate_kernel(
    const float* __restrict__ o, const float* __restrict__ gate,
    const float* __restrict__ nw, float* __restrict__ on)
{
    int gwarp = (blockIdx.x * blockDim.x + threadIdx.x) >> 5;
    int lane  = threadIdx.x & 31;
    if (gwarp >= T_SEQ * NH) return;
    size_t base = (size_t)gwarp * DV;

    float4 x = *(const float4*)&o[base + lane * 4];
    float ss = x.x * x.x + x.y * x.y + x.z * x.z + x.w * x.w;
#pragma unroll
    for (int off = 16; off; off >>= 1)
        ss += __shfl_xor_sync(0xffffffffu, ss, off);
    float rinv = rsqrtf(ss * (1.f / 128.f) + 1e-5f);

    float4 gt  = *(const float4*)&gate[base + lane * 4];
    float4 nwv = *(const float4*)&nw[lane * 4];
    float4 r;
    r.x = x.x * rinv * nwv.x * (gt.x * sigmoidf_(gt.x));
    r.y = x.y * rinv * nwv.y * (gt.y * sigmoidf_(gt.y));
    r.z = x.z * rinv * nwv.z * (gt.z * sigmoidf_(gt.z));
    r.w = x.w * rinv * nwv.w * (gt.w * sigmoidf_(gt.w));
    *(float4*)&on[base + lane * 4] = r;
}

// ---------------------------------------------------------------------------
extern "C" void kernel_launch(void* const* d_in, const int* in_sizes, int n_in,
                              void* d_out, int out_size)
{
    (void)in_sizes; (void)n_in; (void)out_size;
    const float* hs      = (const float*)d_in[0];
    const float* Wq      = (const float*)d_in[1];
    const float* Wk      = (const float*)d_in[2];
    const float* Wv      = (const float*)d_in[3];
    const float* Wb      = (const float*)d_in[4];
    const float* Wa      = (const float*)d_in[5];
    const float* A_log   = (const float*)d_in[6];
    const float* dt_bias = (const float*)d_in[7];
    const float* Wg1     = (const float*)d_in[8];
    const float* Wg2     = (const float*)d_in[9];
    const float* Wgate   = (const float*)d_in[10];
    const float* nw      = (const float*)d_in[11];
    const float* Wo      = (const float*)d_in[12];
    float* out = (float*)d_out;

    float *q, *k, *vpre, *vb, *gateb, *g1, *wc, *bb, *gd, *ob, *onb;
    cudaGetSymbolAddress((void**)&q,     g_q);
    cudaGetSymbolAddress((void**)&k,     g_k);
    cudaGetSymbolAddress((void**)&vpre,  g_vpre);
    cudaGetSymbolAddress((void**)&vb,    g_v);
    cudaGetSymbolAddress((void**)&gateb, g_gate);
    cudaGetSymbolAddress((void**)&g1,    g_g1);
    cudaGetSymbolAddress((void**)&wc,    g_wc);
    cudaGetSymbolAddress((void**)&bb,    g_beta);
    cudaGetSymbolAddress((void**)&gd,    g_gdec);
    cudaGetSymbolAddress((void**)&ob,    g_o);
    cudaGetSymbolAddress((void**)&onb,   g_on);

    auto grid = [](int M, int N) { return dim3((unsigned)((N + 127) / 128),
                                               (unsigned)((M + 127) / 128)); };

    // projections off hidden_states
    gemm_act_kernel<<<grid(T_SEQ, KEY_DIM), 256>>>(hs, Wq, q,     T_SEQ, KEY_DIM, HID, ACT_SILU);
    gemm_act_kernel<<<grid(T_SEQ, KEY_DIM), 256>>>(hs, Wk, k,     T_SEQ, KEY_DIM, HID, ACT_SILU);
    gemm_act_kernel<<<grid(T_SEQ, VAL_DIM), 256>>>(hs, Wv, vpre,  T_SEQ, VAL_DIM, HID, ACT_NONE);
    gemm_act_kernel<<<grid(T_SEQ, VAL_DIM), 256>>>(hs, Wgate, gateb, T_SEQ, VAL_DIM, HID, ACT_NONE);
    small_proj_kernel<<<T_SEQ, 256>>>(hs, Wb, Wa, A_log, dt_bias, bb, gd);
    gemm_act_kernel<<<grid(T_SEQ, GRED), 256>>>(hs, Wg1, g1, T_SEQ, GRED, HID, ACT_SILU);
    gemm_act_kernel<<<grid(T_SEQ, WCONV_N), 256>>>(g1, Wg2, wc, T_SEQ, WCONV_N, GRED, ACT_NONE);

    // dynamic conv -> v
    conv_kernel<<<(T_SEQ * VAL_DIM) / 256, 256>>>(vpre, wc, vb);

    // sequential gated delta rule
    scan_kernel<<<dim3(NH, DV / VPB), 256>>>(q, k, vb, gd, bb, ob);

    // gated RMSNorm + output projection
    rmsgate_kernel<<<(T_SEQ * NH * 32) / 256, 256>>>(ob, gateb, nw, onb);
    gemm_act_kernel<<<grid(T_SEQ, HID), 256>>>(onb, Wo, out, T_SEQ, HID, VAL_DIM, ACT_NONE);
}

// round 2
// speedup vs baseline: 1.3162x; 1.3162x over previous
#include <cuda_runtime.h>
#include <cstdint>
#include <cstddef>

#define T_SEQ   2048
#define HID     1536
#define NH      12
#define DK      128
#define DV      128
#define KEY_DIM 1536
#define VAL_DIM 1536
#define CONV_K  4
#define GRED    192              // HID / 8
#define WCONV_N (VAL_DIM * CONV_K)  // 6144

// ---------------- scratch ----------
__device__ float g_q   [T_SEQ * KEY_DIM];
__device__ float g_k   [T_SEQ * KEY_DIM];
__device__ float g_vpre[T_SEQ * VAL_DIM];
__device__ float g_v   [T_SEQ * VAL_DIM];
__device__ float g_gate[T_SEQ * VAL_DIM];
__device__ float g_g1  [T_SEQ * GRED];
__device__ float g_wc  [T_SEQ * WCONV_N];
__device__ float g_beta[T_SEQ * NH];
__device__ float g_gdec[T_SEQ * NH];
__device__ float g_o   [T_SEQ * VAL_DIM];
__device__ float g_on  [T_SEQ * VAL_DIM];

__device__ __forceinline__ float siluf(float x)    { return x / (1.f + __expf(-x)); }
__device__ __forceinline__ float sigmoidf_(float x){ return 1.f / (1.f + __expf(-x)); }

#define ACT_NONE 0
#define ACT_SILU 1

// =================== tf32x3 tensor-core GEMM ==============================
// C[M,N] = act(A[M,K] @ B[K,N]); BM=BN=128, BK=32, 128 threads (4 warps,
// 2x2 warp grid, 64x64 warp tile). 3xTF32 split for ~fp32 accuracy.
#define SA 36     // A smem row stride (floats): banks 4*gid+tig -> conflict-free
#define SB 136    // B smem row stride (floats): banks 8*tig+gid -> conflict-free
#define KTILE 32
#define GEMM_SMEM ((2 * 128 * SA + 2 * KTILE * SB) * 4)   // 71680 bytes

__device__ __forceinline__ void split_tf32(float x, uint32_t& hi, uint32_t& lo)
{
    uint32_t h;
    asm("cvt.rna.tf32.f32 %0, %1;" : "=r"(h) : "f"(x));
    float l = x - __uint_as_float(h);
    uint32_t lw;
    asm("cvt.rna.tf32.f32 %0, %1;" : "=r"(lw) : "f"(l));
    hi = h; lo = lw;
}

__device__ __forceinline__ void mma_tf32(float* c, const uint32_t* a, const uint32_t* b)
{
    asm volatile(
        "mma.sync.aligned.m16n8k8.row.col.f32.tf32.tf32.f32 "
        "{%0,%1,%2,%3}, {%4,%5,%6,%7}, {%8,%9}, {%0,%1,%2,%3};"
        : "+f"(c[0]), "+f"(c[1]), "+f"(c[2]), "+f"(c[3])
        : "r"(a[0]), "r"(a[1]), "r"(a[2]), "r"(a[3]), "r"(b[0]), "r"(b[1]));
}

__device__ __forceinline__ void cpa16(float* dst, const float* src, int srcsize)
{
    uint32_t d = (uint32_t)__cvta_generic_to_shared(dst);
    asm volatile("cp.async.cg.shared.global [%0], [%1], 16, %2;\n"
                 :: "r"(d), "l"(src), "r"(srcsize));
}

__global__ __launch_bounds__(128) void gemm_tf32_kernel(
    const float* __restrict__ A, const float* __restrict__ B, float* __restrict__ C,
    int M, int N, int K, int act)
{
    extern __shared__ float sm[];
    float* As = sm;                       // [2][128*SA]
    float* Bs = sm + 2 * 128 * SA;        // [2][KTILE*SB]

    const int tid  = threadIdx.x;
    const int lane = tid & 31;
    const int gid  = lane >> 2;
    const int tig  = lane & 3;
    const int wm   = (tid >> 5) >> 1;     // warp row (0..1)
    const int wn   = (tid >> 5) & 1;      // warp col (0..1)
    const int row0 = blockIdx.y * 128;
    const int col0 = blockIdx.x * 128;

    float acc[4][8][4];
#pragma unroll
    for (int mt = 0; mt < 4; mt++)
#pragma unroll
        for (int nt = 0; nt < 8; nt++)
#pragma unroll
            for (int i = 0; i < 4; i++) acc[mt][nt][i] = 0.f;

    const int KT = K / KTILE;

    auto load_tiles = [&](int buf, int kt) {
        float* Ab = As + buf * 128 * SA;
        float* Bb = Bs + buf * KTILE * SB;
#pragma unroll
        for (int i = 0; i < 8; i++) {
            int idx = tid + i * 128;            // 0..1023
            int m   = idx >> 3;
            int kq  = (idx & 7) << 2;
            cpa16(&Ab[m * SA + kq],
                  &A[(size_t)(row0 + m) * K + kt * KTILE + kq], 16);
        }
#pragma unroll
        for (int i = 0; i < 8; i++) {
            int idx = tid + i * 128;
            int kk  = idx >> 5;
            int nq  = (idx & 31) << 2;
            int col = col0 + nq;
            int ok  = (col + 4 <= N);
            cpa16(&Bb[kk * SB + nq],
                  &B[(size_t)(kt * KTILE + kk) * N + (ok ? col : 0)],
                  ok ? 16 : 0);
        }
    };

    load_tiles(0, 0);
    asm volatile("cp.async.commit_group;\n" ::: "memory");

    int buf = 0;
    for (int kt = 0; kt < KT; kt++) {
        if (kt + 1 < KT) {
            load_tiles(buf ^ 1, kt + 1);
            asm volatile("cp.async.commit_group;\n" ::: "memory");
            asm volatile("cp.async.wait_group 1;\n" ::: "memory");
        } else {
            asm volatile("cp.async.wait_group 0;\n" ::: "memory");
        }
        __syncthreads();

        const float* Ab = As + buf * 128 * SA;
        const float* Bb = Bs + buf * KTILE * SB;

#pragma unroll
        for (int ks = 0; ks < 4; ks++) {
            const int kc = ks * 8;
            uint32_t ah[4][4], al[4][4];
#pragma unroll
            for (int mt = 0; mt < 4; mt++) {
                int mb = wm * 64 + mt * 16;
                float x0 = Ab[(mb + gid    ) * SA + kc + tig    ];
                float x1 = Ab[(mb + gid + 8) * SA + kc + tig    ];
                float x2 = Ab[(mb + gid    ) * SA + kc + tig + 4];
                float x3 = Ab[(mb + gid + 8) * SA + kc + tig + 4];
                split_tf32(x0, ah[mt][0], al[mt][0]);
                split_tf32(x1, ah[mt][1], al[mt][1]);
                split_tf32(x2, ah[mt][2], al[mt][2]);
                split_tf32(x3, ah[mt][3], al[mt][3]);
            }
#pragma unroll
            for (int nt = 0; nt < 8; nt++) {
                int nb = wn * 64 + nt * 8;
                float y0 = Bb[(kc + tig    ) * SB + nb + gid];
                float y1 = Bb[(kc + tig + 4) * SB + nb + gid];
                uint32_t bh[2], bl[2];
                split_tf32(y0, bh[0], bl[0]);
                split_tf32(y1, bh[1], bl[1]);
#pragma unroll
                for (int mt = 0; mt < 4; mt++) {
                    mma_tf32(acc[mt][nt], ah[mt], bh);
                    mma_tf32(acc[mt][nt], al[mt], bh);
                    mma_tf32(acc[mt][nt], ah[mt], bl);
                }
            }
        }
        __syncthreads();
        buf ^= 1;
    }

    // epilogue
#pragma unroll
    for (int mt = 0; mt < 4; mt++) {
        int r = row0 + wm * 64 + mt * 16 + gid;
#pragma unroll
        for (int nt = 0; nt < 8; nt++) {
            int c = col0 + wn * 64 + nt * 8 + 2 * tig;
            if (c < N) {
                float v0 = acc[mt][nt][0], v1 = acc[mt][nt][1];
                float v2 = acc[mt][nt][2], v3 = acc[mt][nt][3];
                if (act == ACT_SILU) {
                    v0 = siluf(v0); v1 = siluf(v1);
                    v2 = siluf(v2); v3 = siluf(v3);
                }
                float2 p0 = make_float2(v0, v1);
                float2 p1 = make_float2(v2, v3);
                *(float2*)&C[(size_t)r * N + c]       = p0;
                *(float2*)&C[(size_t)(r + 8) * N + c] = p1;
            }
        }
    }
}

// ------- fused tiny projections: beta = sigmoid(hs@Wb), g = -e^{A}sp(hs@Wa+b)
__global__ __launch_bounds__(256) void small_proj_kernel(
    const float* __restrict__ hs, const float* __restrict__ Wb,
    const float* __restrict__ Wa, const float* __restrict__ A_log,
    const float* __restrict__ dt_bias,
    float* __restrict__ beta, float* __restrict__ gdec)
{
    __shared__ float row[HID];
    const int t = blockIdx.x;
    for (int i = threadIdx.x; i < HID; i += blockDim.x)
        row[i] = hs[(size_t)t * HID + i];
    __syncthreads();

    const int warp = threadIdx.x >> 5;
    const int lane = threadIdx.x & 31;
    for (int oidx = warp; oidx < 2 * NH; oidx += 8) {
        const int  h   = oidx % NH;
        const bool isA = (oidx >= NH);
        const float* W = isA ? Wa : Wb;
        float s = 0.f;
        for (int kk = lane; kk < HID; kk += 32)
            s = fmaf(row[kk], W[(size_t)kk * NH + h], s);
#pragma unroll
        for (int off = 16; off; off >>= 1)
            s += __shfl_xor_sync(0xffffffffu, s, off);
        if (lane == 0) {
            if (isA) {
                float x  = s + dt_bias[h];
                float sp = (x > 20.f) ? x : log1pf(__expf(x));
                gdec[t * NH + h] = -__expf(A_log[h]) * sp;
            } else {
                beta[t * NH + h] = 1.f / (1.f + __expf(-s));
            }
        }
    }
}

// -------- dynamic causal depthwise conv
__global__ __launch_bounds__(256) void conv_kernel(
    const float* __restrict__ vpre, const float* __restrict__ w,
    float* __restrict__ vout)
{
    int idx = blockIdx.x * blockDim.x + threadIdx.x;
    if (idx >= T_SEQ * VAL_DIM) return;
    int t = idx / VAL_DIM;
    int d = idx - t * VAL_DIM;
    float4 wv = *(const float4*)&w[(size_t)t * WCONV_N + d * 4];
    float acc = 0.f;
    if (t >= 3) acc = fmaf(vpre[(size_t)(t - 3) * VAL_DIM + d], wv.x, acc);
    if (t >= 2) acc = fmaf(vpre[(size_t)(t - 2) * VAL_DIM + d], wv.y, acc);
    if (t >= 1) acc = fmaf(vpre[(size_t)(t - 1) * VAL_DIM + d], wv.z, acc);
    acc = fmaf(vpre[(size_t)t * VAL_DIM + d], wv.w, acc);
    vout[idx] = siluf(acc);
}

// ---------------- gated delta-rule scan -----------------------------------
#define SCH 16
#define VPB 16
__global__ __launch_bounds__(256) void scan_kernel(
    const float* __restrict__ q, const float* __restrict__ k,
    const float* __restrict__ v, const float* __restrict__ g,
    const float* __restrict__ beta, float* __restrict__ o)
{
    const int h  = blockIdx.x;
    const int v0 = blockIdx.y * VPB;
    const int tid = threadIdx.x;
    const int vl  = tid >> 4;
    const int kg  = tid & 15;

    __shared__ float ksh[SCH][128];
    __shared__ float qsh[SCH][128];
    __shared__ float vsh[SCH][VPB];
    __shared__ float egs[SCH];
    __shared__ float bts[SCH];

    float S[8];
#pragma unroll
    for (int j = 0; j < 8; j++) S[j] = 0.f;

    const float scale = 0.08838834764831845f;

    for (int t0 = 0; t0 < T_SEQ; t0 += SCH) {
#pragma unroll
        for (int l = 0; l < (SCH * 128) / 256; l++) {
            int idx = tid + l * 256;
            int tt = idx >> 7, kk = idx & 127;
            size_t src = (size_t)(t0 + tt) * KEY_DIM + h * DK + kk;
            ksh[tt][kk] = k[src];
            qsh[tt][kk] = q[src];
        }
        {
            int tt = tid >> 4, vv = tid & 15;
            vsh[tt][vv] = v[(size_t)(t0 + tt) * VAL_DIM + h * DV + v0 + vv];
        }
        if (tid < SCH) {
            egs[tid] = __expf(g[(t0 + tid) * NH + h]);
            bts[tid] = beta[(t0 + tid) * NH + h];
        }
        __syncthreads();

#pragma unroll 4
        for (int tt = 0; tt < SCH; tt++) {
            const float eg = egs[tt];
            const float bt = bts[tt];
            float kr[8], qr[8];
            *(float4*)&kr[0] = *(const float4*)&ksh[tt][kg * 8];
            *(float4*)&kr[4] = *(const float4*)&ksh[tt][kg * 8 + 4];
            *(float4*)&qr[0] = *(const float4*)&qsh[tt][kg * 8];
            *(float4*)&qr[4] = *(const float4*)&qsh[tt][kg * 8 + 4];

            float pa = 0.f, pb = 0.f;
#pragma unroll
            for (int j = 0; j < 8; j += 2) {
                S[j]     *= eg; pa = fmaf(kr[j],     S[j],     pa);
                S[j + 1] *= eg; pb = fmaf(kr[j + 1], S[j + 1], pb);
            }
            float p = pa + pb;
            p += __shfl_xor_sync(0xffffffffu, p, 1);
            p += __shfl_xor_sync(0xffffffffu, p, 2);
            p += __shfl_xor_sync(0xffffffffu, p, 4);
            p += __shfl_xor_sync(0xffffffffu, p, 8);

            const float delta = (vsh[tt][vl] - p) * bt;

            float oa = 0.f, ob = 0.f;
#pragma unroll
            for (int j = 0; j < 8; j += 2) {
                S[j]     = fmaf(kr[j],     delta, S[j]);
                oa       = fmaf(qr[j],     S[j],  oa);
                S[j + 1] = fmaf(kr[j + 1], delta, S[j + 1]);
                ob       = fmaf(qr[j + 1], S[j + 1], ob);
            }
            float op = oa + ob;
            op += __shfl_xor_sync(0xffffffffu, op, 1);
            op += __shfl_xor_sync(0xffffffffu, op, 2);
            op += __shfl_xor_sync(0xffffffffu, op, 4);
            op += __shfl_xor_sync(0xffffffffu, op, 8);

            if (kg == 0)
                o[(size_t)(t0 + tt) * VAL_DIM + h * DV + v0 + vl] = op * scale;
        }
        __syncthreads();
    }
}

// ------- gated RMSNorm -----------------------------------------------------
__global__ __launch_bounds__(256) void rmsgate_kernel(
    const float* __restrict__ o, const float* __restrict__ gate,
    const float* __restrict__ nw, float* __restrict__ on)
{
    int gwarp = (blockIdx.x * blockDim.x + threadIdx.x) >> 5;
    int lane  = threadIdx.x & 31;
    if (gwarp >= T_SEQ * NH) return;
    size_t base = (size_t)gwarp * DV;

    float4 x = *(const float4*)&o[base + lane * 4];
    float ss = x.x * x.x + x.y * x.y + x.z * x.z + x.w * x.w;
#pragma unroll
    for (int off = 16; off; off >>= 1)
        ss += __shfl_xor_sync(0xffffffffu, ss, off);
    float rinv = rsqrtf(ss * (1.f / 128.f) + 1e-5f);

    float4 gt  = *(const float4*)&gate[base + lane * 4];
    float4 nwv = *(const float4*)&nw[lane * 4];
    float4 r;
    r.x = x.x * rinv * nwv.x * (gt.x * sigmoidf_(gt.x));
    r.y = x.y * rinv * nwv.y * (gt.y * sigmoidf_(gt.y));
    r.z = x.z * rinv * nwv.z * (gt.z * sigmoidf_(gt.z));
    r.w = x.w * rinv * nwv.w * (gt.w * sigmoidf_(gt.w));
    *(float4*)&on[base + lane * 4] = r;
}

// ---------------------------------------------------------------------------
extern "C" void kernel_launch(void* const* d_in, const int* in_sizes, int n_in,
                              void* d_out, int out_size)
{
    (void)in_sizes; (void)n_in; (void)out_size;
    const float* hs      = (const float*)d_in[0];
    const float* Wq      = (const float*)d_in[1];
    const float* Wk      = (const float*)d_in[2];
    const float* Wv      = (const float*)d_in[3];
    const float* Wb      = (const float*)d_in[4];
    const float* Wa      = (const float*)d_in[5];
    const float* A_log   = (const float*)d_in[6];
    const float* dt_bias = (const float*)d_in[7];
    const float* Wg1     = (const float*)d_in[8];
    const float* Wg2     = (const float*)d_in[9];
    const float* Wgate   = (const float*)d_in[10];
    const float* nw      = (const float*)d_in[11];
    const float* Wo      = (const float*)d_in[12];
    float* out = (float*)d_out;

    float *q, *k, *vpre, *vb, *gateb, *g1, *wc, *bb, *gd, *ob, *onb;
    cudaGetSymbolAddress((void**)&q,     g_q);
    cudaGetSymbolAddress((void**)&k,     g_k);
    cudaGetSymbolAddress((void**)&vpre,  g_vpre);
    cudaGetSymbolAddress((void**)&vb,    g_v);
    cudaGetSymbolAddress((void**)&gateb, g_gate);
    cudaGetSymbolAddress((void**)&g1,    g_g1);
    cudaGetSymbolAddress((void**)&wc,    g_wc);
    cudaGetSymbolAddress((void**)&bb,    g_beta);
    cudaGetSymbolAddress((void**)&gd,    g_gdec);
    cudaGetSymbolAddress((void**)&ob,    g_o);
    cudaGetSymbolAddress((void**)&onb,   g_on);

    cudaFuncSetAttribute(gemm_tf32_kernel,
                         cudaFuncAttributeMaxDynamicSharedMemorySize, GEMM_SMEM);

    auto grid = [](int M, int N) { return dim3((unsigned)((N + 127) / 128),
                                               (unsigned)((M + 127) / 128)); };

    gemm_tf32_kernel<<<grid(T_SEQ, KEY_DIM), 128, GEMM_SMEM>>>(hs, Wq, q,     T_SEQ, KEY_DIM, HID, ACT_SILU);
    gemm_tf32_kernel<<<grid(T_SEQ, KEY_DIM), 128, GEMM_SMEM>>>(hs, Wk, k,     T_SEQ, KEY_DIM, HID, ACT_SILU);
    gemm_tf32_kernel<<<grid(T_SEQ, VAL_DIM), 128, GEMM_SMEM>>>(hs, Wv, vpre,  T_SEQ, VAL_DIM, HID, ACT_NONE);
    gemm_tf32_kernel<<<grid(T_SEQ, VAL_DIM), 128, GEMM_SMEM>>>(hs, Wgate, gateb, T_SEQ, VAL_DIM, HID, ACT_NONE);
    small_proj_kernel<<<T_SEQ, 256>>>(hs, Wb, Wa, A_log, dt_bias, bb, gd);
    gemm_tf32_kernel<<<grid(T_SEQ, GRED), 128, GEMM_SMEM>>>(hs, Wg1, g1, T_SEQ, GRED, HID, ACT_SILU);
    gemm_tf32_kernel<<<grid(T_SEQ, WCONV_N), 128, GEMM_SMEM>>>(g1, Wg2, wc, T_SEQ, WCONV_N, GRED, ACT_NONE);

    conv_kernel<<<(T_SEQ * VAL_DIM) / 256, 256>>>(vpre, wc, vb);

    scan_kernel<<<dim3(NH, DV / VPB), 256>>>(q, k, vb, gd, bb, ob);

    rmsgate_kernel<<<(T_SEQ * NH * 32) / 256, 256>>>(ob, gateb, nw, onb);
    gemm_tf32_kernel<<<grid(T_SEQ, HID), 128, GEMM_SMEM>>>(onb, Wo, out, T_SEQ, HID, VAL_DIM, ACT_NONE);
}